// round 12
// baseline (speedup 1.0000x reference)
#include <cuda_runtime.h>
#include <cuda_fp8.h>
#include <cstdint>

#define B_   4
#define H_   32
#define W_   32
#define C_   64
#define F_   128
#define NF   8
#define KC   (C_ * NF)       // 512 fp8 bytes per kernel position
#define KTOT (9 * KC)        // 4608
#define HP   34
#define WP   34
#define NPIX (B_ * H_ * W_)  // 4096
#define NOUT (NPIX * F_)     // 524288

#define LDB  144             // smem row stride in BYTES

// Scratch (device globals — no allocation)
__device__ __align__(16) uint8_t g_Xf[B_ * HP * WP * KC]; // ~2.4 MB e4m3
__device__ __align__(16) uint8_t g_Wt[F_ * KTOT];         // ~0.6 MB e4m3

__device__ __forceinline__ int load_bits(const int* bp) {
    if (bp == nullptr) return 4;
    int b = bp[0];
    if (b < 1 || b > 30) b = (int)__int_as_float(b);
    if (b < 1 || b > 30) b = 4;
    return b;
}

// e4m3 encodings of integers 0..7 and 8..15 (all exact in e4m3)
#define E4M3_LUT0 0x4E4C4A4844403800ull
#define E4M3_LUT1 0x5756555453525150ull

__device__ __forceinline__ uint32_t int_to_e4m3(int v) {
    if (v < 8)  return (uint32_t)((E4M3_LUT0 >> (v * 8)) & 0xFF);
    if (v < 16) return (uint32_t)((E4M3_LUT1 >> ((v - 8) * 8)) & 0xFF);
    return (uint32_t)__nv_cvt_float_to_fp8((float)v, __NV_SATFINITE, __NV_E4M3);
}

__device__ uint64_t feat_pack_slow(int xi, int bits) {
    uint64_t p = 0;
#pragma unroll
    for (int m = 1; m <= 8; m++)
        p |= (uint64_t)int_to_e4m3((xi * m) >> bits) << (8 * (m - 1));
    return p;
}
__device__ uint64_t wt_pack_slow(int wi, int bits) {
    int s = (wi > 0) - (wi < 0);
    int m = (wi < 0 ? -wi : wi) & ((1 << bits) - 1);
    uint64_t p = 0;
    if (m >= 1 && m <= 8) p = (uint64_t)(s > 0 ? 0x38u : 0xB8u) << (8 * (m - 1));
    return p;
}

#define NC4    (C_ / 4)                    // 16
#define FEAT_T (B_ * HP * WP * NC4)        // 73984 (4 channels per thread)
#define WT_T   (9 * C_ * F_ / 4)           // 18432 (4 filters per thread)
#define INIT_T (NOUT / 8)                  // 65536 (2 float4 per thread)
#define PREP_T (FEAT_T + WT_T + INIT_T)    // 157952

// ---------------------------------------------------------------------------
// Fused prep, vectorized x4, smem pack-LUTs.
// ---------------------------------------------------------------------------
__global__ void prep_kernel(const float* __restrict__ x, const float* __restrict__ kern,
                            const float4* __restrict__ bias4, float4* __restrict__ out4,
                            const int* __restrict__ bitsPtr) {
    __shared__ uint64_t featLUT[16];
    __shared__ uint64_t wtLUT[16];
    const int bits = load_bits(bitsPtr);
    const int t = threadIdx.x;
    if (t < 16) {
        featLUT[t] = feat_pack_slow(t, bits);
    } else if (t < 32) {
        wtLUT[t - 16] = wt_pack_slow((t - 16) - 8, bits);
    }
    __syncthreads();

    int idx = blockIdx.x * blockDim.x + t;
    if (idx >= PREP_T) return;

    if (idx < FEAT_T) {
        int c4 = idx & 15;
        int rr = idx >> 4;
        int wp = rr % WP; rr /= WP;
        int hp = rr % HP;
        int b  = rr / HP;

        uint64_t v[4] = {0ull, 0ull, 0ull, 0ull};
        if (hp >= 1 && hp <= H_ && wp >= 1 && wp <= W_) {
            const float4 xv = *(const float4*)(
                x + ((((b * H_) + (hp - 1)) * W_ + (wp - 1)) * C_ + c4 * 4));
            int xi0 = (int)xv.x, xi1 = (int)xv.y, xi2 = (int)xv.z, xi3 = (int)xv.w;
            v[0] = ((unsigned)xi0 < 16u) ? featLUT[xi0] : feat_pack_slow(xi0, bits);
            v[1] = ((unsigned)xi1 < 16u) ? featLUT[xi1] : feat_pack_slow(xi1, bits);
            v[2] = ((unsigned)xi2 < 16u) ? featLUT[xi2] : feat_pack_slow(xi2, bits);
            v[3] = ((unsigned)xi3 < 16u) ? featLUT[xi3] : feat_pack_slow(xi3, bits);
        }
        uint4* dst = (uint4*)(g_Xf + (size_t)idx * 32);
        dst[0] = *(uint4*)&v[0];
        dst[1] = *(uint4*)&v[2];
    } else if (idx < FEAT_T + WT_T) {
        int i  = idx - FEAT_T;
        int f4 = i & 31;
        int rr = i >> 5;
        int c  = rr & 63;
        int pos = rr >> 6;

        const float4 kv = *(const float4*)(kern + (size_t)(pos * C_ + c) * F_ + f4 * 4);
        const float kf[4] = {kv.x, kv.y, kv.z, kv.w};
#pragma unroll
        for (int j = 0; j < 4; j++) {
            int wi = (int)kf[j];
            uint64_t p = ((unsigned)(wi + 8) < 16u) ? wtLUT[wi + 8] : wt_pack_slow(wi, bits);
            *(uint64_t*)(g_Wt + (size_t)(f4 * 4 + j) * KTOT + pos * KC + c * 8) = p;
        }
    } else {
        int t2 = idx - FEAT_T - WT_T;          // [0, 65536)
        float4 bv = bias4[t2 & 31];
        out4[t2]          = bv;                // 65536 % 32 == 0 -> same bias slot
        out4[t2 + INIT_T] = bv;
    }
}

__global__ void relu_kernel(float4* __restrict__ out) {
    int t = blockIdx.x * blockDim.x + threadIdx.x;
    if (t >= NOUT / 4) return;
    float4 v = out[t];
    v.x = fmaxf(v.x, 0.f); v.y = fmaxf(v.y, 0.f);
    v.z = fmaxf(v.z, 0.f); v.w = fmaxf(v.w, 0.f);
    out[t] = v;
}

// ---------------------------------------------------------------------------
// FP8 GEMM (R5 core, reg-slimmed for 4 CTAs/SM): block 64(M) x 128(N),
// 8 warps 2x4, grid (64, 9). mma m16n8k32 e4m3 -> f32. cp.async double buffer.
// ---------------------------------------------------------------------------
__device__ __forceinline__ void mma_e4m3(float c[4], const uint32_t a[4], const uint32_t b0,
                                         const uint32_t b1) {
    asm volatile(
        "mma.sync.aligned.m16n8k32.row.col.f32.e4m3.e4m3.f32 "
        "{%0,%1,%2,%3}, {%4,%5,%6,%7}, {%8,%9}, {%0,%1,%2,%3};\n"
        : "+f"(c[0]), "+f"(c[1]), "+f"(c[2]), "+f"(c[3])
        : "r"(a[0]), "r"(a[1]), "r"(a[2]), "r"(a[3]), "r"(b0), "r"(b1));
}
__device__ __forceinline__ void ldsm_x4(uint32_t r[4], uint32_t addr) {
    asm volatile("ldmatrix.sync.aligned.m8n8.x4.shared.b16 {%0,%1,%2,%3}, [%4];"
                 : "=r"(r[0]), "=r"(r[1]), "=r"(r[2]), "=r"(r[3]) : "r"(addr));
}
__device__ __forceinline__ void cp16(uint32_t smemAddr, const void* gmem) {
    asm volatile("cp.async.cg.shared.global [%0], [%1], 16;" :: "r"(smemAddr), "l"(gmem));
}

#define ASLAB (64 * LDB)     // bytes per A buffer (64 rows)
#define BSLAB (128 * LDB)    // bytes per B buffer (128 rows)
#define SMEMB (2 * ASLAB + 2 * BSLAB)   // 55296 bytes

__global__ __launch_bounds__(256, 4) void gemm_kernel(float* __restrict__ out) {
    extern __shared__ uint8_t sm[];
    uint8_t* As = sm;               // [2][64][LDB]
    uint8_t* Bs = sm + 2 * ASLAB;   // [2][128][LDB]

    const int tid = threadIdx.x;
    const int pos = blockIdx.y;
    const int di  = pos / 3, dj = pos - di * 3;
    const int p0  = blockIdx.x * 64;

    const int cr = tid >> 3;          // 0..31
    const int cc = tid & 7;           // 16B chunk within 128B row

    // A sources: two pixel rows (wrap-dependent -> keep 2 pointers)
    const uint8_t* aSrc0;
    const uint8_t* aSrc1;
    {
        int p = p0 + cr;
        aSrc0 = g_Xf + ((((p >> 10) * HP + ((p >> 5) & 31) + di) * WP) + (p & 31) + dj) * KC + cc * 16;
        p += 32;
        aSrc1 = g_Xf + ((((p >> 10) * HP + ((p >> 5) & 31) + di) * WP) + (p & 31) + dj) * KC + cc * 16;
    }
    // B source base: rows differ by constant 32*KTOT
    const uint8_t* bSrc0 = g_Wt + (size_t)cr * KTOT + pos * KC + cc * 16;
    // smem dst bases: rows differ by constant 32*LDB
    const uint32_t aDst0 = (uint32_t)__cvta_generic_to_shared(As + cr * LDB + cc * 16);
    const uint32_t bDst0 = (uint32_t)__cvta_generic_to_shared(Bs + cr * LDB + cc * 16);

    const int wa = tid >> 5, lane = tid & 31;
    const int wm = wa & 1, wn = wa >> 1;
    const int fRow  = lane & 15;
    const int fColB = (lane >> 4) << 4;

    float acc[2][4][4];
#pragma unroll
    for (int mi = 0; mi < 2; mi++)
#pragma unroll
        for (int j = 0; j < 4; j++)
#pragma unroll
            for (int e = 0; e < 4; e++) acc[mi][j][e] = 0.0f;

    // prefetch slab 0
    cp16(aDst0,            aSrc0);
    cp16(aDst0 + 32 * LDB, aSrc1);
#pragma unroll
    for (int ps = 0; ps < 4; ps++)
        cp16(bDst0 + ps * 32 * LDB, bSrc0 + (size_t)ps * 32 * KTOT);
    asm volatile("cp.async.commit_group;");

#pragma unroll 1
    for (int ks = 0; ks < 4; ks++) {
        const int cur = ks & 1;
        if (ks < 3) {
            const uint32_t bufA = ((ks + 1) & 1) * ASLAB;
            const uint32_t bufB = ((ks + 1) & 1) * BSLAB;
            const int k0 = (ks + 1) * 128;
            cp16(aDst0 + bufA,            aSrc0 + k0);
            cp16(aDst0 + bufA + 32 * LDB, aSrc1 + k0);
#pragma unroll
            for (int ps = 0; ps < 4; ps++)
                cp16(bDst0 + bufB + ps * 32 * LDB, bSrc0 + (size_t)ps * 32 * KTOT + k0);
            asm volatile("cp.async.commit_group;");
            asm volatile("cp.async.wait_group 1;");
        } else {
            asm volatile("cp.async.wait_group 0;");
        }
        __syncthreads();

        const uint8_t* Ab = As + cur * ASLAB;
        const uint8_t* Bb = Bs + cur * BSLAB;
#pragma unroll
        for (int kk = 0; kk < 4; kk++) {
            const int kcB = kk * 32;
            uint32_t a[2][4], b[2][4];
#pragma unroll
            for (int mi = 0; mi < 2; mi++) {
                uint32_t ad = (uint32_t)__cvta_generic_to_shared(
                    Ab + (wm * 32 + mi * 16 + fRow) * LDB + kcB + fColB);
                ldsm_x4(a[mi], ad);
            }
#pragma unroll
            for (int ni = 0; ni < 2; ni++) {
                uint32_t bd = (uint32_t)__cvta_generic_to_shared(
                    Bb + (wn * 32 + ni * 16 + fRow) * LDB + kcB + fColB);
                ldsm_x4(b[ni], bd);
            }
#pragma unroll
            for (int mi = 0; mi < 2; mi++)
#pragma unroll
                for (int j = 0; j < 4; j++)
                    mma_e4m3(acc[mi][j], a[mi], b[j >> 1][j & 1], b[j >> 1][(j & 1) + 2]);
        }
        __syncthreads();
    }

    // ---- split-K epilogue: exact-integer f32 atomics ----
    const int g = lane >> 2, t4 = lane & 3;
#pragma unroll
    for (int mi = 0; mi < 2; mi++) {
        int r0 = p0 + wm * 32 + mi * 16 + g;
#pragma unroll
        for (int j = 0; j < 4; j++) {
            int ccol = wn * 32 + j * 8 + t4 * 2;
            atomicAdd(&out[r0 * F_ + ccol],           acc[mi][j][0]);
            atomicAdd(&out[r0 * F_ + ccol + 1],       acc[mi][j][1]);
            atomicAdd(&out[(r0 + 8) * F_ + ccol],     acc[mi][j][2]);
            atomicAdd(&out[(r0 + 8) * F_ + ccol + 1], acc[mi][j][3]);
        }
    }
}

// ---------------------------------------------------------------------------
extern "C" void kernel_launch(void* const* d_in, const int* in_sizes, int n_in,
                              void* d_out, int out_size) {
    const float* x    = (const float*)d_in[0];
    const float* kern = (const float*)d_in[1];
    const float* bias = (const float*)d_in[2];
    const int*   bits = (n_in >= 4) ? (const int*)d_in[3] : nullptr;
    float* out = (float*)d_out;

    static int smemSet = 0;
    if (!smemSet) {
        cudaFuncSetAttribute(gemm_kernel, cudaFuncAttributeMaxDynamicSharedMemorySize, SMEMB);
        smemSet = 1;
    }

    prep_kernel<<<(PREP_T + 255) / 256, 256>>>(x, kern, (const float4*)bias,
                                               (float4*)out, bits);
    dim3 gg(NPIX / 64, 9);
    gemm_kernel<<<gg, 256, SMEMB>>>(out);
    relu_kernel<<<(NOUT / 4 + 255) / 256, 256>>>((float4*)out);
}

// round 13
// speedup vs baseline: 1.1639x; 1.1639x over previous
#include <cuda_runtime.h>
#include <cuda_fp8.h>
#include <cstdint>

#define B_   4
#define H_   32
#define W_   32
#define C_   64
#define F_   128
#define NF   8
#define KC   (C_ * NF)       // 512 fp8 bytes per kernel position
#define KTOT (9 * KC)        // 4608
#define HP   34
#define WP   34
#define NPIX (B_ * H_ * W_)  // 4096
#define NOUT (NPIX * F_)     // 524288

// Scratch (device globals — no allocation)
__device__ __align__(16) uint8_t g_Xf[B_ * HP * WP * KC]; // ~2.4 MB e4m3
__device__ __align__(16) uint8_t g_Wt[F_ * KTOT];         // ~0.6 MB e4m3

__device__ __forceinline__ int load_bits(const int* bp) {
    if (bp == nullptr) return 4;
    int b = bp[0];
    if (b < 1 || b > 30) b = (int)__int_as_float(b);
    if (b < 1 || b > 30) b = 4;
    return b;
}

// e4m3 encodings of integers 0..7 and 8..15 (all exact in e4m3)
#define E4M3_LUT0 0x4E4C4A4844403800ull
#define E4M3_LUT1 0x5756555453525150ull

__device__ __forceinline__ uint32_t int_to_e4m3(int v) {
    if (v < 8)  return (uint32_t)((E4M3_LUT0 >> (v * 8)) & 0xFF);
    if (v < 16) return (uint32_t)((E4M3_LUT1 >> ((v - 8) * 8)) & 0xFF);
    return (uint32_t)__nv_cvt_float_to_fp8((float)v, __NV_SATFINITE, __NV_E4M3);
}

__device__ uint64_t feat_pack_slow(int xi, int bits) {
    uint64_t p = 0;
#pragma unroll
    for (int m = 1; m <= 8; m++)
        p |= (uint64_t)int_to_e4m3((xi * m) >> bits) << (8 * (m - 1));
    return p;
}
__device__ uint64_t wt_pack_slow(int wi, int bits) {
    int s = (wi > 0) - (wi < 0);
    int m = (wi < 0 ? -wi : wi) & ((1 << bits) - 1);
    uint64_t p = 0;
    if (m >= 1 && m <= 8) p = (uint64_t)(s > 0 ? 0x38u : 0xB8u) << (8 * (m - 1));
    return p;
}

#define NC4    (C_ / 4)                    // 16
#define FEAT_T (B_ * HP * WP * NC4)        // 73984 (4 channels per thread)
#define WT_T   (9 * C_ * F_ / 4)           // 18432 (4 filters per thread)
#define INIT_T (NOUT / 8)                  // 65536 (2 float4 per thread)
#define PREP_T (FEAT_T + WT_T + INIT_T)    // 157952

// ---------------------------------------------------------------------------
// Fused prep (R12, verified): feature/weight expand via smem LUT + bias init.
// ---------------------------------------------------------------------------
__global__ void prep_kernel(const float* __restrict__ x, const float* __restrict__ kern,
                            const float4* __restrict__ bias4, float4* __restrict__ out4,
                            const int* __restrict__ bitsPtr) {
    __shared__ uint64_t featLUT[16];
    __shared__ uint64_t wtLUT[16];
    const int bits = load_bits(bitsPtr);
    const int t = threadIdx.x;
    if (t < 16) {
        featLUT[t] = feat_pack_slow(t, bits);
    } else if (t < 32) {
        wtLUT[t - 16] = wt_pack_slow((t - 16) - 8, bits);
    }
    __syncthreads();

    int idx = blockIdx.x * blockDim.x + t;
    if (idx >= PREP_T) return;

    if (idx < FEAT_T) {
        int c4 = idx & 15;
        int rr = idx >> 4;
        int wp = rr % WP; rr /= WP;
        int hp = rr % HP;
        int b  = rr / HP;

        uint64_t v[4] = {0ull, 0ull, 0ull, 0ull};
        if (hp >= 1 && hp <= H_ && wp >= 1 && wp <= W_) {
            const float4 xv = *(const float4*)(
                x + ((((b * H_) + (hp - 1)) * W_ + (wp - 1)) * C_ + c4 * 4));
            int xi0 = (int)xv.x, xi1 = (int)xv.y, xi2 = (int)xv.z, xi3 = (int)xv.w;
            v[0] = ((unsigned)xi0 < 16u) ? featLUT[xi0] : feat_pack_slow(xi0, bits);
            v[1] = ((unsigned)xi1 < 16u) ? featLUT[xi1] : feat_pack_slow(xi1, bits);
            v[2] = ((unsigned)xi2 < 16u) ? featLUT[xi2] : feat_pack_slow(xi2, bits);
            v[3] = ((unsigned)xi3 < 16u) ? featLUT[xi3] : feat_pack_slow(xi3, bits);
        }
        uint4* dst = (uint4*)(g_Xf + (size_t)idx * 32);
        dst[0] = *(uint4*)&v[0];
        dst[1] = *(uint4*)&v[2];
    } else if (idx < FEAT_T + WT_T) {
        int i  = idx - FEAT_T;
        int f4 = i & 31;
        int rr = i >> 5;
        int c  = rr & 63;
        int pos = rr >> 6;

        const float4 kv = *(const float4*)(kern + (size_t)(pos * C_ + c) * F_ + f4 * 4);
        const float kf[4] = {kv.x, kv.y, kv.z, kv.w};
#pragma unroll
        for (int j = 0; j < 4; j++) {
            int wi = (int)kf[j];
            uint64_t p = ((unsigned)(wi + 8) < 16u) ? wtLUT[wi + 8] : wt_pack_slow(wi, bits);
            *(uint64_t*)(g_Wt + (size_t)(f4 * 4 + j) * KTOT + pos * KC + c * 8) = p;
        }
    } else {
        int t2 = idx - FEAT_T - WT_T;
        float4 bv = bias4[t2 & 31];
        out4[t2]          = bv;
        out4[t2 + INIT_T] = bv;
    }
}

__global__ void relu_kernel(float4* __restrict__ out) {
    int t = blockIdx.x * blockDim.x + threadIdx.x;
    if (t >= NOUT / 4) return;
    float4 v = out[t];
    v.x = fmaxf(v.x, 0.f); v.y = fmaxf(v.y, 0.f);
    v.z = fmaxf(v.z, 0.f); v.w = fmaxf(v.w, 0.f);
    out[t] = v;
}

// ---------------------------------------------------------------------------
// FP8 GEMM, single-phase: full K=512 resident in SMEM, ONE barrier, then 16
// barrier-free k32 steps. Block 64(M) x 128(N), 8 warps 2x4, grid (64, 9).
// ---------------------------------------------------------------------------
__device__ __forceinline__ void mma_e4m3(float c[4], const uint32_t a[4], const uint32_t b0,
                                         const uint32_t b1) {
    asm volatile(
        "mma.sync.aligned.m16n8k32.row.col.f32.e4m3.e4m3.f32 "
        "{%0,%1,%2,%3}, {%4,%5,%6,%7}, {%8,%9}, {%0,%1,%2,%3};\n"
        : "+f"(c[0]), "+f"(c[1]), "+f"(c[2]), "+f"(c[3])
        : "r"(a[0]), "r"(a[1]), "r"(a[2]), "r"(a[3]), "r"(b0), "r"(b1));
}
__device__ __forceinline__ void ldsm_x4(uint32_t r[4], uint32_t addr) {
    asm volatile("ldmatrix.sync.aligned.m8n8.x4.shared.b16 {%0,%1,%2,%3}, [%4];"
                 : "=r"(r[0]), "=r"(r[1]), "=r"(r[2]), "=r"(r[3]) : "r"(addr));
}
__device__ __forceinline__ void cp16(uint32_t smemAddr, const void* gmem) {
    asm volatile("cp.async.cg.shared.global [%0], [%1], 16;" :: "r"(smemAddr), "l"(gmem));
}

#define LDR   528                       // smem row stride bytes (512 data + 16 pad)
#define ABYTES (64 * LDR)               // 33792
#define SMEMB  (ABYTES + 128 * LDR)     // 101376 total

__global__ __launch_bounds__(256) void gemm_kernel(float* __restrict__ out) {
    extern __shared__ uint8_t sm[];
    uint8_t* As = sm;                   // [64][LDR]
    uint8_t* Bs = sm + ABYTES;          // [128][LDR]

    const int tid = threadIdx.x;
    const int pos = blockIdx.y;
    const int di  = pos / 3, dj = pos - di * 3;
    const int p0  = blockIdx.x * 64;

    const int col  = tid & 31;          // 16B chunk column (0..31)
    const int rbase = tid >> 5;         // row base (0..7)

    // ---- A: 64 rows x 32 chunks; thread does rows rbase+8i, i=0..7 ----
#pragma unroll
    for (int i = 0; i < 8; i++) {
        int r = rbase + 8 * i;
        int p = p0 + r;
        int bb = p >> 10, hh = (p >> 5) & 31, ww = p & 31;
        const uint8_t* src = g_Xf + ((bb * HP + hh + di) * WP + (ww + dj)) * KC + col * 16;
        cp16((uint32_t)__cvta_generic_to_shared(As + r * LDR + col * 16), src);
    }
    // ---- B: 128 rows x 32 chunks; rows rbase+8i, i=0..15 ----
#pragma unroll
    for (int i = 0; i < 16; i++) {
        int r = rbase + 8 * i;
        const uint8_t* src = g_Wt + (size_t)r * KTOT + pos * KC + col * 16;
        cp16((uint32_t)__cvta_generic_to_shared(Bs + r * LDR + col * 16), src);
    }
    asm volatile("cp.async.commit_group;");

    // fragment addressing
    const int wa = tid >> 5, lane = tid & 31;
    const int wm = wa & 1, wn = wa >> 1;
    const int fRow  = lane & 15;
    const int fColB = (lane >> 4) << 4;
    const uint32_t aBase = (uint32_t)__cvta_generic_to_shared(
        As + (wm * 32 + fRow) * LDR + fColB);
    const uint32_t bBase = (uint32_t)__cvta_generic_to_shared(
        Bs + (wn * 32 + fRow) * LDR + fColB);

    float acc[2][4][4];
#pragma unroll
    for (int mi = 0; mi < 2; mi++)
#pragma unroll
        for (int j = 0; j < 4; j++)
#pragma unroll
            for (int e = 0; e < 4; e++) acc[mi][j][e] = 0.0f;

    asm volatile("cp.async.wait_group 0;");
    __syncthreads();                    // the ONLY barrier

#pragma unroll
    for (int kk = 0; kk < 16; kk++) {
        const int kcB = kk * 32;
        uint32_t a[2][4], b[2][4];
#pragma unroll
        for (int mi = 0; mi < 2; mi++)
            ldsm_x4(a[mi], aBase + mi * 16 * LDR + kcB);
#pragma unroll
        for (int ni = 0; ni < 2; ni++)
            ldsm_x4(b[ni], bBase + ni * 16 * LDR + kcB);
#pragma unroll
        for (int mi = 0; mi < 2; mi++)
#pragma unroll
            for (int j = 0; j < 4; j++)
                mma_e4m3(acc[mi][j], a[mi], b[j >> 1][j & 1], b[j >> 1][(j & 1) + 2]);
    }

    // ---- split-K epilogue: exact-integer f32 atomics ----
    const int g = lane >> 2, t4 = lane & 3;
#pragma unroll
    for (int mi = 0; mi < 2; mi++) {
        int r0 = p0 + wm * 32 + mi * 16 + g;
#pragma unroll
        for (int j = 0; j < 4; j++) {
            int ccol = wn * 32 + j * 8 + t4 * 2;
            atomicAdd(&out[r0 * F_ + ccol],           acc[mi][j][0]);
            atomicAdd(&out[r0 * F_ + ccol + 1],       acc[mi][j][1]);
            atomicAdd(&out[(r0 + 8) * F_ + ccol],     acc[mi][j][2]);
            atomicAdd(&out[(r0 + 8) * F_ + ccol + 1], acc[mi][j][3]);
        }
    }
}

// ---------------------------------------------------------------------------
extern "C" void kernel_launch(void* const* d_in, const int* in_sizes, int n_in,
                              void* d_out, int out_size) {
    const float* x    = (const float*)d_in[0];
    const float* kern = (const float*)d_in[1];
    const float* bias = (const float*)d_in[2];
    const int*   bits = (n_in >= 4) ? (const int*)d_in[3] : nullptr;
    float* out = (float*)d_out;

    static int smemSet = 0;
    if (!smemSet) {
        cudaFuncSetAttribute(gemm_kernel, cudaFuncAttributeMaxDynamicSharedMemorySize, SMEMB);
        smemSet = 1;
    }

    prep_kernel<<<(PREP_T + 255) / 256, 256>>>(x, kern, (const float4*)bias,
                                               (float4*)out, bits);
    dim3 gg(NPIX / 64, 9);
    gemm_kernel<<<gg, 256, SMEMB>>>(out);
    relu_kernel<<<(NOUT / 4 + 255) / 256, 256>>>((float4*)out);
}